// round 5
// baseline (speedup 1.0000x reference)
#include <cuda_runtime.h>
#include <cstdint>

// Shapes: x[8,64,512,512] f32, W[64,64], b[64], seg_w[4,4] -> out[8,64,512,512]
#define Bb 8
#define Cc 64
#define Oo 64
#define HW 512
#define PLANE_F4 (HW*HW/4)      // 65536 float4 per (b,c) plane
#define BAND_F4  (128*HW/4)     // 16384 float4 per 128-row band
#define NITEM    4096           // 2048 pool + 2048 bcast items
#define GRID     1184           // 8 CTAs/SM on 148 SMs -> exactly one resident wave

// scratch (__device__ globals: allocation-free rule)
__device__ float g_pooled[Bb*Cc*16];    // [b][c][i*4+j]
__device__ float g_weighted[Bb*Oo*16];  // [b][o][i*4+j]
__device__ int   g_poolcnt[Bb];
__device__ int   g_flag[Bb];
__device__ int   g_ticket;

__global__ void init_kernel()
{
    if (threadIdx.x < Bb) { g_poolcnt[threadIdx.x] = 0; g_flag[threadIdx.x] = 0; }
    if (threadIdx.x == 31) g_ticket = 0;
}

// Item schedule (pos -> kind,batch,t):
//   [0,768)      : pool b0, b1, b2
//   [768,3328)   : 5 groups of 512: bcast b(g) (256) then pool b(g+3) (256), g=0..4
//   [3328,4096)  : bcast b5, b6, b7
// Pool items of batch b always precede bcast items of batch b in ticket order,
// so with the whole grid resident every flag spin makes progress.
__global__ void __launch_bounds__(256, 8) fused_kernel(
    const float4* __restrict__ x,
    const float*  __restrict__ Wm,
    const float*  __restrict__ bias,
    const float*  __restrict__ segw,
    float4* __restrict__ out)
{
    __shared__ float ws[8];
    __shared__ int   s_pos;
    __shared__ int   s_last;

    const int tid  = threadIdx.x;
    const int warp = tid >> 5;
    const int jseg = (tid & 127) >> 5;   // column segment, loop-invariant

    for (;;) {
        if (tid == 0) s_pos = atomicAdd(&g_ticket, 1);
        __syncthreads();
        const int pos = s_pos;
        if (pos >= NITEM) return;
        __syncthreads();   // protect s_pos before next iteration overwrites it

        int kind, b, t;
        if (pos < 768)       { kind = 0; b = pos >> 8; t = pos & 255; }
        else if (pos < 3328) { int g = (pos - 768) >> 9; int r = (pos - 768) & 511;
                               if (r < 256) { kind = 1; b = g;     t = r; }
                               else         { kind = 0; b = g + 3; t = r & 255; } }
        else                 { kind = 1; b = 5 + ((pos - 3328) >> 8); t = pos & 255; }

        if (kind == 0) {
            // ---- pool item (b, c = t>>2, i = t&3): segment means over a 128-row band
            const int c  = t >> 2, i = t & 3;
            const int bc = b * Cc + c;
            const float4* base = x + (size_t)bc * PLANE_F4 + (size_t)i * BAND_F4;

            float acc = 0.0f;
            #pragma unroll 4
            for (int idx = tid; idx < BAND_F4; idx += 256) {
                float4 v = __ldcs(&base[idx]);
                acc += (v.x + v.y) + (v.z + v.w);
            }
            #pragma unroll
            for (int off = 16; off; off >>= 1)
                acc += __shfl_xor_sync(0xffffffffu, acc, off);
            if ((tid & 31) == 0) ws[warp] = acc;
            __syncthreads();

            if (tid == 0) {
                const float inv = 1.0f / 16384.0f;
                float* dst = g_pooled + bc * 16 + i * 4;
                dst[0] = (ws[0] + ws[4]) * inv;
                dst[1] = (ws[1] + ws[5]) * inv;
                dst[2] = (ws[2] + ws[6]) * inv;
                dst[3] = (ws[3] + ws[7]) * inv;
                __threadfence();                       // release pooled values
                int old = atomicAdd(&g_poolcnt[b], 1);
                s_last = (old == Cc * 4 - 1);          // last arrival runs the linear
            }
            __syncthreads();

            if (s_last) {
                // ---- tiny linear + seg scale for batch b: 1024 outputs
                #pragma unroll
                for (int k = 0; k < 4; k++) {
                    const int idx2 = tid + k * 256;
                    const int o = idx2 >> 4, ij = idx2 & 15;
                    const float* p  = g_pooled + (b * Cc) * 16 + ij;
                    const float* wr = Wm + o * Cc;
                    float a = bias[o];
                    #pragma unroll 8
                    for (int cc = 0; cc < Cc; cc++)
                        a = fmaf(__ldcg(&p[cc * 16]), wr[cc], a);
                    g_weighted[(b * Oo + o) * 16 + ij] = a * segw[ij];
                }
                __threadfence();                       // release weighted values
                __syncthreads();
                if (tid == 0) atomicExch(&g_flag[b], 1);
            }
        } else {
            // ---- bcast item (b, o = t>>2, i = t&3): fill a 128-row band
            const int o  = t >> 2, i = t & 3;
            const int bo = b * Oo + o;

            if (tid == 0) {
                while (atomicAdd(&g_flag[b], 0) == 0) __nanosleep(200);
                __threadfence();                       // acquire
            }
            __syncthreads();

            const float v = __ldcg(&g_weighted[bo * 16 + i * 4 + jseg]);
            const float4 f = make_float4(v, v, v, v);
            float4* base = out + (size_t)bo * PLANE_F4 + (size_t)i * BAND_F4;

            #pragma unroll 4
            for (int idx = tid; idx < BAND_F4; idx += 256)
                __stcs(&base[idx], f);
        }
        __syncthreads();   // ws / s_last safe for next iteration
    }
}

extern "C" void kernel_launch(void* const* d_in, const int* in_sizes, int n_in,
                              void* d_out, int out_size)
{
    const float4* x    = (const float4*)d_in[0];
    const float*  Wm   = (const float*)d_in[1];
    const float*  bias = (const float*)d_in[2];
    const float*  segw = (const float*)d_in[3];
    float4* out = (float4*)d_out;

    init_kernel<<<1, 32>>>();
    fused_kernel<<<GRID, 256>>>(x, Wm, bias, segw, out);
}

// round 6
// speedup vs baseline: 1.3115x; 1.3115x over previous
#include <cuda_runtime.h>
#include <cstdint>

// Shapes: x[8,64,512,512] f32, W[64,64], b[64], seg_w[4,4] -> out[8,64,512,512]
// SEG=4 -> 128x128 blocks; a "band" = one (b,c,i) slab of 128 rows = 16384 float4.
#define Bb 8
#define Cc 64
#define Oo 64
#define N4      33554432          // total float4 in x / out
#define BAND_F4 16384             // float4 per band
#define GRID    1184              // 8 CTAs/SM * 148 SMs
#define CHUNK   28416             // ceil-ish N4/GRID, multiple of 128

// scratch (__device__ globals: allocation-free rule)
__device__ float g_pooled[Bb*Cc*16];   // [b][c][i*4+j], mean-scaled

__global__ void init_kernel()
{
    int idx = blockIdx.x * 256 + threadIdx.x;
    if (idx < Bb*Cc*16) g_pooled[idx] = 0.0f;
}

// ---------------------------------------------------------------------------
// Kernel 1: pool. Each CTA owns flat float4 range [s,e) (uniform work, no
// ragged waves). For each band intersecting the range: accumulate, block
// reduce per column-segment j, atomicAdd the 4 partials into g_pooled.
// A band (16384 f4) intersects at most 2 chunks (28416 f4), so each pooled
// cell receives exactly <=2 contributions -> bitwise deterministic.
// Thread's j is loop-invariant: range starts are multiples of 128.
// ---------------------------------------------------------------------------
__global__ void __launch_bounds__(256, 8) pool_kernel(const float4* __restrict__ x)
{
    const int tid  = threadIdx.x;
    const int warp = tid >> 5;

    const int s = blockIdx.x * CHUNK;
    const int e = min(s + CHUNK, N4);
    if (s >= e) return;

    __shared__ float ws[8];

    const int g0 = s >> 14;                 // first band index
    const int g1 = (e - 1) >> 14;           // last band index

    for (int g = g0; g <= g1; g++) {
        const int lo = max(s, g << 14);
        const int hi = min(e, (g + 1) << 14);

        float acc = 0.0f;
        #pragma unroll 4
        for (int idx = lo + tid; idx < hi; idx += 256) {
            float4 v = __ldcs(&x[idx]);
            acc += (v.x + v.y) + (v.z + v.w);
        }
        #pragma unroll
        for (int off = 16; off; off >>= 1)
            acc += __shfl_xor_sync(0xffffffffu, acc, off);
        if ((tid & 31) == 0) ws[warp] = acc;   // warp w holds j = w&3
        __syncthreads();

        if (tid < 4) {
            const float inv = 1.0f / 16384.0f;
            float total = (ws[tid] + ws[tid + 4]) * inv;
            // band g -> bc = g>>2, i = g&3 ; cell = bc*16 + i*4 + j
            atomicAdd(&g_pooled[(g >> 2) * 16 + (g & 3) * 4 + tid], total);
        }
        __syncthreads();   // ws reuse safe
    }
}

// ---------------------------------------------------------------------------
// Kernel 2: broadcast with inlined linear. Each CTA owns the same flat range.
// Per band-intersection, every thread computes (warp-uniform, L1-hot) the
// 64-channel dot for its (b,o,i,j) cell, then streams constant float4 stores.
// ---------------------------------------------------------------------------
__global__ void __launch_bounds__(256, 8) bcast_kernel(
    const float* __restrict__ Wm,
    const float* __restrict__ bias,
    const float* __restrict__ segw,
    float4* __restrict__ out)
{
    const int tid = threadIdx.x;

    const int s = blockIdx.x * CHUNK;
    const int e = min(s + CHUNK, N4);
    if (s >= e) return;

    const int g0 = s >> 14;
    const int g1 = (e - 1) >> 14;

    for (int g = g0; g <= g1; g++) {
        const int lo = max(s, g << 14);
        const int hi = min(e, (g + 1) << 14);

        // band g -> bo = g>>2, i = g&3 ; thread column segment:
        const int j  = ((lo + tid) & 127) >> 5;   // lo multiple of 128
        const int bo = g >> 2;
        const int i  = g & 3;
        const int b  = bo >> 6;
        const int o  = bo & (Oo - 1);
        const int ij = i * 4 + j;

        // tiny linear: dot over channels (warp-uniform addresses -> broadcast)
        const float* p  = g_pooled + (b * Cc) * 16 + ij;
        const float* wr = Wm + o * Cc;
        float a = bias[o];
        #pragma unroll 8
        for (int c = 0; c < Cc; c++)
            a = fmaf(p[c * 16], wr[c], a);
        const float v = a * segw[ij];
        const float4 f = make_float4(v, v, v, v);

        #pragma unroll 4
        for (int idx = lo + tid; idx < hi; idx += 256)
            __stcs(&out[idx], f);
    }
}

// ---------------------------------------------------------------------------
extern "C" void kernel_launch(void* const* d_in, const int* in_sizes, int n_in,
                              void* d_out, int out_size)
{
    const float4* x    = (const float4*)d_in[0];
    const float*  Wm   = (const float*)d_in[1];
    const float*  bias = (const float*)d_in[2];
    const float*  segw = (const float*)d_in[3];
    float4* out = (float4*)d_out;

    init_kernel<<<(Bb*Cc*16 + 255) / 256, 256>>>();
    pool_kernel<<<GRID, 256>>>(x);
    bcast_kernel<<<GRID, 256>>>(Wm, bias, segw, out);
}

// round 7
// speedup vs baseline: 1.3167x; 1.0039x over previous
#include <cuda_runtime.h>
#include <cstdint>

// Shapes: x[8,64,512,512] f32, W[64,64], b[64], seg_w[4,4] -> out[8,64,512,512]
// SEG=4 -> 128x128 blocks; a "band" = one (b,c,i) slab of 128 rows = 16384 float4.
#define Bb 8
#define Cc 64
#define Oo 64
#define N4      33554432          // total float4 in x / out
#define BAND_F4 16384             // float4 per band
#define GRID    1184              // 8 CTAs/SM * 148 SMs
#define CHUNK   28416             // ceil-ish N4/GRID, multiple of 128

// scratch (__device__ globals: allocation-free rule)
__device__ float g_pooled[Bb*Cc*16];   // [b][c][i*4+j], mean-scaled

__global__ void init_kernel()
{
    int idx = blockIdx.x * 256 + threadIdx.x;
    if (idx < Bb*Cc*16) g_pooled[idx] = 0.0f;
}

// ---------------------------------------------------------------------------
// Kernel 1: pool. Each CTA owns flat float4 range [s,e) (uniform work, no
// ragged waves). For each band intersecting the range: accumulate, block
// reduce per column-segment j, atomicAdd the 4 partials into g_pooled.
// A band (16384 f4) intersects at most 2 chunks (28416 f4), so each pooled
// cell receives exactly <=2 contributions -> bitwise deterministic.
// Thread's j is loop-invariant: range starts are multiples of 128.
// ---------------------------------------------------------------------------
__global__ void __launch_bounds__(256, 8) pool_kernel(const float4* __restrict__ x)
{
    const int tid  = threadIdx.x;
    const int warp = tid >> 5;

    const int s = blockIdx.x * CHUNK;
    const int e = min(s + CHUNK, N4);
    if (s >= e) return;

    __shared__ float ws[8];

    const int g0 = s >> 14;                 // first band index
    const int g1 = (e - 1) >> 14;           // last band index

    for (int g = g0; g <= g1; g++) {
        const int lo = max(s, g << 14);
        const int hi = min(e, (g + 1) << 14);

        float acc = 0.0f;
        #pragma unroll 4
        for (int idx = lo + tid; idx < hi; idx += 256) {
            float4 v = __ldcs(&x[idx]);
            acc += (v.x + v.y) + (v.z + v.w);
        }
        #pragma unroll
        for (int off = 16; off; off >>= 1)
            acc += __shfl_xor_sync(0xffffffffu, acc, off);
        if ((tid & 31) == 0) ws[warp] = acc;   // warp w holds j = w&3
        __syncthreads();

        if (tid < 4) {
            const float inv = 1.0f / 16384.0f;
            float total = (ws[tid] + ws[tid + 4]) * inv;
            // band g -> bc = g>>2, i = g&3 ; cell = bc*16 + i*4 + j
            atomicAdd(&g_pooled[(g >> 2) * 16 + (g & 3) * 4 + tid], total);
        }
        __syncthreads();   // ws reuse safe
    }
}

// ---------------------------------------------------------------------------
// Kernel 2: broadcast with inlined linear. Each CTA owns the same flat range.
// Per band-intersection, every thread computes (warp-uniform, L1-hot) the
// 64-channel dot for its (b,o,i,j) cell, then streams constant float4 stores.
// ---------------------------------------------------------------------------
__global__ void __launch_bounds__(256, 8) bcast_kernel(
    const float* __restrict__ Wm,
    const float* __restrict__ bias,
    const float* __restrict__ segw,
    float4* __restrict__ out)
{
    const int tid = threadIdx.x;

    const int s = blockIdx.x * CHUNK;
    const int e = min(s + CHUNK, N4);
    if (s >= e) return;

    const int g0 = s >> 14;
    const int g1 = (e - 1) >> 14;

    for (int g = g0; g <= g1; g++) {
        const int lo = max(s, g << 14);
        const int hi = min(e, (g + 1) << 14);

        // band g -> bo = g>>2, i = g&3 ; thread column segment:
        const int j  = ((lo + tid) & 127) >> 5;   // lo multiple of 128
        const int bo = g >> 2;
        const int i  = g & 3;
        const int b  = bo >> 6;
        const int o  = bo & (Oo - 1);
        const int ij = i * 4 + j;

        // tiny linear: dot over channels (warp-uniform addresses -> broadcast)
        const float* p  = g_pooled + (b * Cc) * 16 + ij;
        const float* wr = Wm + o * Cc;
        float a = bias[o];
        #pragma unroll 8
        for (int c = 0; c < Cc; c++)
            a = fmaf(p[c * 16], wr[c], a);
        const float v = a * segw[ij];
        const float4 f = make_float4(v, v, v, v);

        #pragma unroll 4
        for (int idx = lo + tid; idx < hi; idx += 256)
            __stcs(&out[idx], f);
    }
}

// ---------------------------------------------------------------------------
extern "C" void kernel_launch(void* const* d_in, const int* in_sizes, int n_in,
                              void* d_out, int out_size)
{
    const float4* x    = (const float4*)d_in[0];
    const float*  Wm   = (const float*)d_in[1];
    const float*  bias = (const float*)d_in[2];
    const float*  segw = (const float*)d_in[3];
    float4* out = (float4*)d_out;

    init_kernel<<<(Bb*Cc*16 + 255) / 256, 256>>>();
    pool_kernel<<<GRID, 256>>>(x);
    bcast_kernel<<<GRID, 256>>>(Wm, bias, segw, out);
}

// round 8
// speedup vs baseline: 1.3594x; 1.0325x over previous
#include <cuda_runtime.h>
#include <cstdint>

// Shapes: x[8,64,512,512] f32, W[64,64], b[64], seg_w[4,4] -> out[8,64,512,512]
// SEG=4 -> 128x128 blocks. A "band" = one (b,c,i) slab of 128 rows = 16384 float4.
// 2048 bands total; 1024 CTAs x 2 bands each = perfectly uniform single wave.
#define Bb 8
#define Cc 64
#define Oo 64
#define BAND_F4 16384
#define GRID    1024

// scratch (__device__ global: allocation-free rule)
__device__ float g_pooled[Bb*Cc*16];   // [b][c][i*4+j], mean-scaled

// ---------------------------------------------------------------------------
// Kernel 1: segment mean pool. CTA k owns bands 2k and 2k+1.
// Per band: every thread has fixed column segment j = (tid&127)>>5,
// accumulate float4 stream, warp-shuffle reduce, combine 8 warps -> 4 means.
// ---------------------------------------------------------------------------
__global__ void __launch_bounds__(256, 8) pool_kernel(const float4* __restrict__ x)
{
    const int tid  = threadIdx.x;
    const int warp = tid >> 5;

    __shared__ float ws[8];

    #pragma unroll
    for (int sub = 0; sub < 2; sub++) {
        const int g = blockIdx.x * 2 + sub;          // band index 0..2047
        const float4* base = x + (size_t)g * BAND_F4;

        float acc = 0.0f;
        #pragma unroll 8
        for (int idx = tid; idx < BAND_F4; idx += 256) {
            float4 v = base[idx];
            acc += (v.x + v.y) + (v.z + v.w);
        }
        #pragma unroll
        for (int off = 16; off; off >>= 1)
            acc += __shfl_xor_sync(0xffffffffu, acc, off);
        if ((tid & 31) == 0) ws[warp] = acc;         // warp w covers j = w&3
        __syncthreads();

        if (tid < 4) {
            const float inv = 1.0f / 16384.0f;
            // band g -> bc = g>>2, i = g&3 ; cell = bc*16 + i*4 + j
            g_pooled[(g >> 2) * 16 + (g & 3) * 4 + tid] =
                (ws[tid] + ws[tid + 4]) * inv;
        }
        __syncthreads();                             // ws reuse safe
    }
}

// ---------------------------------------------------------------------------
// Kernel 2: broadcast with inlined linear. CTA k owns bands 2k and 2k+1.
// Per band: each thread computes the 64-channel dot for its (b,o,i,j) cell
// (warp-uniform addresses -> L1/const broadcast, ~64 FMA), then streams
// constant float4 stores over its column-segment slice of the band.
// ---------------------------------------------------------------------------
__global__ void __launch_bounds__(256, 8) bcast_kernel(
    const float* __restrict__ Wm,
    const float* __restrict__ bias,
    const float* __restrict__ segw,
    float4* __restrict__ out)
{
    const int tid = threadIdx.x;
    const int j   = (tid & 127) >> 5;                // fixed column segment

    #pragma unroll
    for (int sub = 0; sub < 2; sub++) {
        const int g  = blockIdx.x * 2 + sub;         // band index 0..2047
        const int bo = g >> 2;                       // b*O + o
        const int i  = g & 3;
        const int b  = bo >> 6;
        const int o  = bo & (Oo - 1);
        const int ij = i * 4 + j;

        const float* p  = g_pooled + (b * Cc) * 16 + ij;
        const float* wr = Wm + o * Cc;
        float a = bias[o];
        #pragma unroll 8
        for (int c = 0; c < Cc; c++)
            a = fmaf(p[c * 16], wr[c], a);
        const float v = a * segw[ij];
        const float4 f = make_float4(v, v, v, v);

        float4* base = out + (size_t)g * BAND_F4;
        #pragma unroll 8
        for (int idx = tid; idx < BAND_F4; idx += 256)
            base[idx] = f;
    }
}

// ---------------------------------------------------------------------------
extern "C" void kernel_launch(void* const* d_in, const int* in_sizes, int n_in,
                              void* d_out, int out_size)
{
    const float4* x    = (const float4*)d_in[0];
    const float*  Wm   = (const float*)d_in[1];
    const float*  bias = (const float*)d_in[2];
    const float*  segw = (const float*)d_in[3];
    float4* out = (float4*)d_out;

    pool_kernel<<<GRID, 256>>>(x);
    bcast_kernel<<<GRID, 256>>>(Wm, bias, segw, out);
}